// round 14
// baseline (speedup 1.0000x reference)
#include <cuda_runtime.h>
#include <cuda_bf16.h>
#include <cstdint>
#include <cstring>

// Problem constants
#define BB 4
#define SS 1024
#define DD 768
#define HH 12
#define DH 64
#define RR 129          // 2K+1, K=64
#define KWIN 64

#define MTOT (BB * SS)  // 4096

// ---------------- scratch (no allocation allowed) ----------------
__device__ float g_Qp[MTOT * DD];      // reinterpreted: bf16 QsH/QsL
__device__ float g_Kp[MTOT * DD];      // reinterpreted: bf16 KsH/KsL
__device__ float g_Vp[MTOT * DD];      // reinterpreted: bf16 VsH/VsL

__device__ __nv_bfloat16 g_qh[MTOT * DD],  g_ql[MTOT * DD];
__device__ __nv_bfloat16 g_kh[MTOT * DD],  g_kl[MTOT * DD];
__device__ __nv_bfloat16 g_vh[MTOT * DD],  g_vl[MTOT * DD];
__device__ __nv_bfloat16 g_ch[MTOT * DD],  g_cl[MTOT * DD];
__device__ __nv_bfloat16 g_wqh[DD * DD], g_wql[DD * DD];
__device__ __nv_bfloat16 g_wkh[DD * DD], g_wkl[DD * DD];
__device__ __nv_bfloat16 g_wvh[DD * DD], g_wvl[DD * DD];
__device__ __nv_bfloat16 g_woh[DD * DD], g_wol[DD * DD];

// packed V^T: [b*HH+h][d(64)][pair(512)]
__device__ uint32_t g_vtH[BB * HH * DH * (SS / 2)];
__device__ uint32_t g_vtL[BB * HH * DH * (SS / 2)];

// ---------------- cp.async helpers ----------------
__device__ __forceinline__ uint32_t smem_u32(const void* p) {
    uint32_t a;
    asm("{ .reg .u64 t; cvta.to.shared.u64 t, %1; cvt.u32.u64 %0, t; }"
        : "=r"(a) : "l"(p));
    return a;
}
#define CP_ASYNC16(sa, ga) \
    asm volatile("cp.async.cg.shared.global [%0], [%1], 16;" :: "r"(sa), "l"(ga))
#define CP_COMMIT() asm volatile("cp.async.commit_group;" ::: "memory")
#define CP_WAIT1()  asm volatile("cp.async.wait_group 1;" ::: "memory")
#define CP_WAIT0()  asm volatile("cp.async.wait_group 0;" ::: "memory")

// ---------------- fp32 -> bf16 hi/lo split ----------------
__device__ __forceinline__ void split4(const float* __restrict__ x,
                                       __nv_bfloat16* __restrict__ hi,
                                       __nv_bfloat16* __restrict__ lo, int i)
{
    float4 v = *(const float4*)&x[i];
    float vv[4] = {v.x, v.y, v.z, v.w};
    uint16_t h[4], l[4];
    #pragma unroll
    for (int p = 0; p < 4; p++) {
        __nv_bfloat16 hb = __float2bfloat16(vv[p]);
        __nv_bfloat16 lb = __float2bfloat16(vv[p] - __bfloat162float(hb));
        h[p] = __bfloat16_as_ushort(hb);
        l[p] = __bfloat16_as_ushort(lb);
    }
    *(uint2*)&hi[i] = make_uint2(((uint32_t)h[1] << 16) | h[0], ((uint32_t)h[3] << 16) | h[2]);
    *(uint2*)&lo[i] = make_uint2(((uint32_t)l[1] << 16) | l[0], ((uint32_t)l[3] << 16) | l[2]);
}

__global__ __launch_bounds__(256) void split_all_kernel(
    const float* __restrict__ i0, __nv_bfloat16* i0h, __nv_bfloat16* i0l,
    const float* __restrict__ i1, __nv_bfloat16* i1h, __nv_bfloat16* i1l,
    const float* __restrict__ i2, __nv_bfloat16* i2h, __nv_bfloat16* i2l,
    const float* __restrict__ w0, __nv_bfloat16* w0h, __nv_bfloat16* w0l,
    const float* __restrict__ w1, __nv_bfloat16* w1h, __nv_bfloat16* w1l,
    const float* __restrict__ w2, __nv_bfloat16* w2h, __nv_bfloat16* w2l,
    const float* __restrict__ w3, __nv_bfloat16* w3h, __nv_bfloat16* w3l,
    int nin, int nw)
{
    int i = (blockIdx.x * 256 + threadIdx.x) * 4;
    int y = blockIdx.y;
    int n = (y < 3) ? nin : nw;
    if (i >= n) return;
    const float* x; __nv_bfloat16 *hi, *lo;
    switch (y) {
        case 0: x = i0; hi = i0h; lo = i0l; break;
        case 1: x = i1; hi = i1h; lo = i1l; break;
        case 2: x = i2; hi = i2h; lo = i2l; break;
        case 3: x = w0; hi = w0h; lo = w0l; break;
        case 4: x = w1; hi = w1h; lo = w1l; break;
        case 5: x = w2; hi = w2h; lo = w2l; break;
        default: x = w3; hi = w3h; lo = w3l; break;
    }
    split4(x, hi, lo, i);
}

// ---------------- mma.sync helper ----------------
__device__ __forceinline__ void mma16816(float* d, const uint32_t* a, const uint32_t* b) {
    asm volatile("mma.sync.aligned.m16n8k16.row.col.f32.bf16.bf16.f32 "
        "{%0,%1,%2,%3}, {%4,%5,%6,%7}, {%8,%9}, {%0,%1,%2,%3};"
        : "+f"(d[0]), "+f"(d[1]), "+f"(d[2]), "+f"(d[3])
        : "r"(a[0]), "r"(a[1]), "r"(a[2]), "r"(a[3]), "r"(b[0]), "r"(b[1]));
}

// ---------------- bf16-split GEMM, 64x128 tile, cp.async 2-stage ----------------
#define SP 40
#define AARR 5120
#define WARR 10240
#define GBUF 30720
#define GSMB (2 * GBUF)

__device__ __forceinline__ void gemm_issue64(
    uint32_t sb, int buf, int tid, int bm, int bn, int k0, int Kd,
    const __nv_bfloat16* __restrict__ Ah, const __nv_bfloat16* __restrict__ Al,
    const __nv_bfloat16* __restrict__ Wh, const __nv_bfloat16* __restrict__ Wl)
{
    uint32_t bo = sb + buf * GBUF;
    {
        int rowA = tid >> 2, cc = (tid & 3) * 8;
        size_t ga = (size_t)(bm + rowA) * Kd + k0 + cc;
        uint32_t so = (uint32_t)(rowA * SP + cc) * 2;
        CP_ASYNC16(bo + so,        Ah + ga);
        CP_ASYNC16(bo + AARR + so, Al + ga);
    }
    #pragma unroll
    for (int it = 0; it < 2; it++) {
        int i = tid + it * 256;
        int rowW = i >> 2, cc = (i & 3) * 8;
        size_t gw = (size_t)(bn + rowW) * Kd + k0 + cc;
        uint32_t so = (uint32_t)(rowW * SP + cc) * 2;
        CP_ASYNC16(bo + 2 * AARR + so,        Wh + gw);
        CP_ASYNC16(bo + 2 * AARR + WARR + so, Wl + gw);
    }
    CP_COMMIT();
}

__device__ __forceinline__ void gemm_body64(
    const __nv_bfloat16* __restrict__ Ah, const __nv_bfloat16* __restrict__ Al,
    const __nv_bfloat16* __restrict__ Wh, const __nv_bfloat16* __restrict__ Wl,
    const float* __restrict__ bias, float* __restrict__ C,
    __nv_bfloat16* __restrict__ Ch, __nv_bfloat16* __restrict__ Cl,
    int M, int N, int Kd)
{
    extern __shared__ char gsm[];
    uint32_t sb = smem_u32(gsm);

    const int tid = threadIdx.x;
    const int bm = blockIdx.y * 64, bn = blockIdx.x * 128;
    const int warp = tid >> 5, lane = tid & 31;
    const int wm = warp & 1, wn = warp >> 1;
    const int g = lane >> 2, t = lane & 3;

    float d[2][4][4] = {};

    const int nch = Kd / 32;
    gemm_issue64(sb, 0, tid, bm, bn, 0, Kd, Ah, Al, Wh, Wl);

    for (int c = 0; c < nch; c++) {
        if (c + 1 < nch) {
            gemm_issue64(sb, (c + 1) & 1, tid, bm, bn, (c + 1) * 32, Kd, Ah, Al, Wh, Wl);
            CP_WAIT1();
        } else {
            CP_WAIT0();
        }
        __syncthreads();

        const char* st = gsm + (c & 1) * GBUF;
        const __nv_bfloat16* sAh = (const __nv_bfloat16*)st;
        const __nv_bfloat16* sAl = (const __nv_bfloat16*)(st + AARR);
        const __nv_bfloat16* sWh = (const __nv_bfloat16*)(st + 2 * AARR);
        const __nv_bfloat16* sWl = (const __nv_bfloat16*)(st + 2 * AARR + WARR);

        #pragma unroll
        for (int ks = 0; ks < 2; ks++) {
            const int kk = ks * 16 + 2 * t;
            uint32_t bh[4][2], bl[4][2];
            #pragma unroll
            for (int ni = 0; ni < 4; ni++) {
                int rb = (wn * 32 + ni * 8 + g) * SP;
                bh[ni][0] = *(const uint32_t*)&sWh[rb + kk];
                bh[ni][1] = *(const uint32_t*)&sWh[rb + kk + 8];
                bl[ni][0] = *(const uint32_t*)&sWl[rb + kk];
                bl[ni][1] = *(const uint32_t*)&sWl[rb + kk + 8];
            }
            #pragma unroll
            for (int mi = 0; mi < 2; mi++) {
                int r0 = (wm * 32 + mi * 16 + g) * SP;
                int r1 = r0 + 8 * SP;
                uint32_t ah[4], al[4];
                ah[0] = *(const uint32_t*)&sAh[r0 + kk];
                ah[1] = *(const uint32_t*)&sAh[r1 + kk];
                ah[2] = *(const uint32_t*)&sAh[r0 + kk + 8];
                ah[3] = *(const uint32_t*)&sAh[r1 + kk + 8];
                al[0] = *(const uint32_t*)&sAl[r0 + kk];
                al[1] = *(const uint32_t*)&sAl[r1 + kk];
                al[2] = *(const uint32_t*)&sAl[r0 + kk + 8];
                al[3] = *(const uint32_t*)&sAl[r1 + kk + 8];
                #pragma unroll
                for (int ni = 0; ni < 4; ni++) {
                    mma16816(d[mi][ni], ah, bh[ni]);
                    mma16816(d[mi][ni], ah, bl[ni]);
                    mma16816(d[mi][ni], al, bh[ni]);
                }
            }
        }
        __syncthreads();
    }

    #pragma unroll
    for (int mi = 0; mi < 2; mi++) {
        int r0 = bm + wm * 32 + mi * 16 + g;
        #pragma unroll
        for (int ni = 0; ni < 4; ni++) {
            int c0 = bn + wn * 32 + ni * 8 + 2 * t;
            float b0 = bias[c0], b1 = bias[c0 + 1];
            float v00 = d[mi][ni][0] + b0, v01 = d[mi][ni][1] + b1;
            float v10 = d[mi][ni][2] + b0, v11 = d[mi][ni][3] + b1;
            if (Ch) {
                uint32_t hp0, lp0, hp1, lp1;
                asm("cvt.rn.bf16x2.f32 %0, %1, %2;" : "=r"(hp0) : "f"(v01), "f"(v00));
                asm("cvt.rn.bf16x2.f32 %0, %1, %2;" : "=r"(hp1) : "f"(v11), "f"(v10));
                float h00 = __uint_as_float(hp0 << 16);
                float h01 = __uint_as_float(hp0 & 0xffff0000u);
                float h10 = __uint_as_float(hp1 << 16);
                float h11 = __uint_as_float(hp1 & 0xffff0000u);
                asm("cvt.rn.bf16x2.f32 %0, %1, %2;" : "=r"(lp0) : "f"(v01 - h01), "f"(v00 - h00));
                asm("cvt.rn.bf16x2.f32 %0, %1, %2;" : "=r"(lp1) : "f"(v11 - h11), "f"(v10 - h10));
                *(uint32_t*)&Ch[(size_t)r0 * N + c0]       = hp0;
                *(uint32_t*)&Cl[(size_t)r0 * N + c0]       = lp0;
                *(uint32_t*)&Ch[(size_t)(r0 + 8) * N + c0] = hp1;
                *(uint32_t*)&Cl[(size_t)(r0 + 8) * N + c0] = lp1;
            } else {
                C[(size_t)r0 * N + c0]           = v00;
                C[(size_t)r0 * N + c0 + 1]       = v01;
                C[(size_t)(r0 + 8) * N + c0]     = v10;
                C[(size_t)(r0 + 8) * N + c0 + 1] = v11;
            }
        }
    }
}

__global__ __launch_bounds__(256, 2) void gemm_qkv(
    const __nv_bfloat16* qh, const __nv_bfloat16* ql,
    const __nv_bfloat16* wqh, const __nv_bfloat16* wql, const float* WQb,
    __nv_bfloat16* QsH, __nv_bfloat16* QsL,
    const __nv_bfloat16* kh, const __nv_bfloat16* kl,
    const __nv_bfloat16* wkh, const __nv_bfloat16* wkl, const float* WKb,
    __nv_bfloat16* KsH, __nv_bfloat16* KsL,
    const __nv_bfloat16* vh, const __nv_bfloat16* vl,
    const __nv_bfloat16* wvh, const __nv_bfloat16* wvl, const float* WVb,
    __nv_bfloat16* VsH, __nv_bfloat16* VsL)
{
    if (blockIdx.z == 0)
        gemm_body64(qh, ql, wqh, wql, WQb, nullptr, QsH, QsL, MTOT, DD, DD);
    else if (blockIdx.z == 1)
        gemm_body64(kh, kl, wkh, wkl, WKb, nullptr, KsH, KsL, MTOT, DD, DD);
    else
        gemm_body64(vh, vl, wvh, wvl, WVb, nullptr, VsH, VsL, MTOT, DD, DD);
}

__global__ __launch_bounds__(256, 2) void gemm_o(
    const __nv_bfloat16* ch, const __nv_bfloat16* cl,
    const __nv_bfloat16* woh, const __nv_bfloat16* wol, const float* WOb,
    float* out)
{
    gemm_body64(ch, cl, woh, wol, WOb, out, nullptr, nullptr, MTOT, DD, DD);
}

// ---------------- V transpose+pack ----------------
__global__ __launch_bounds__(256) void vtrans_kernel(
    const __nv_bfloat16* __restrict__ VsH, const __nv_bfloat16* __restrict__ VsL,
    uint32_t* __restrict__ vtH, uint32_t* __restrict__ vtL)
{
    const int vt = blockIdx.x & 7;
    const int h  = (blockIdx.x >> 3) % HH;
    const int b  = blockIdx.x / (8 * HH);
    const int tid = threadIdx.x;
    const size_t obase = ((size_t)(b * HH + h)) * DH * (SS / 2) + vt * 64;

    for (int i = tid; i < 1024; i += 256) {
        int s = i >> 9, r = i & 511;
        int p = r >> 3, dg = r & 7;
        const __nv_bfloat16* src = s ? VsL : VsH;
        uint32_t* dst = s ? vtL : vtH;
        size_t base = ((size_t)(b * SS) + vt * 128 + 2 * p) * DD + h * DH + dg * 8;
        uint4 w0 = *(const uint4*)&src[base];
        uint4 w1 = *(const uint4*)&src[base + DD];
        uint16_t a0[8], a1[8];
        memcpy(a0, &w0, 16);
        memcpy(a1, &w1, 16);
        #pragma unroll
        for (int j = 0; j < 8; j++)
            dst[obase + (size_t)(dg * 8 + j) * (SS / 2) + p] =
                (uint32_t)a0[j] | ((uint32_t)a1[j] << 16);
    }
}

// ---------------- flash-style fused relative attention ----------------
// smem layout (bytes):
//   qH/qL   : [0, 9216)           bf16 32x72 each
//   region A: [9216, 52224)       K chunk bf16[128][72] / V chunk u32[64][84] / embK / embV
//   sSc     : [52224, 69120)      fp32 [32][132] score chunk
//   pH/pL   : [69120, 90624)      bf16 [32][168]   (also fp32 staging for reduce)
//   sW      : [90624, 111104)     fp32 [32][160] rel table -> w buckets
//   sInv    : [111104, 111232)
//   sSum    : [111232, 111360)
#define KP 72
#define PP 168
#define VP 84
#define WP 160
#define SCP 132
#define OFF_Q  0
#define QSTRIDE 4608
#define OFF_A  9216
#define ASTRIDE 21504
#define OFF_SC 52224
#define OFF_P  69120
#define PSTRIDE 10752
#define OFF_W  90624
#define OFF_I  111104
#define OFF_SU 111232
#define ASM_BYTES 111360

__global__ __launch_bounds__(512, 2) void attn_mma(
    const __nv_bfloat16* __restrict__ QsH, const __nv_bfloat16* __restrict__ QsL,
    const __nv_bfloat16* __restrict__ KsH, const __nv_bfloat16* __restrict__ KsL,
    const uint32_t* __restrict__ vtH, const uint32_t* __restrict__ vtL,
    const float* __restrict__ embK, const float* __restrict__ embV,
    float* __restrict__ attn_out,
    __nv_bfloat16* __restrict__ ctxH, __nv_bfloat16* __restrict__ ctxL)
{
    extern __shared__ char smc[];
    uint32_t sb = smem_u32(smc);
    __nv_bfloat16* qH = (__nv_bfloat16*)(smc + OFF_Q);
    __nv_bfloat16* qL = (__nv_bfloat16*)(smc + OFF_Q + QSTRIDE);
    __nv_bfloat16* aH = (__nv_bfloat16*)(smc + OFF_A);
    __nv_bfloat16* aL = (__nv_bfloat16*)(smc + OFF_A + ASTRIDE);
    uint32_t* vH = (uint32_t*)(smc + OFF_A);
    uint32_t* vL = (uint32_t*)(smc + OFF_A + ASTRIDE);
    float* sSc = (float*)(smc + OFF_SC);
    __nv_bfloat16* pH = (__nv_bfloat16*)(smc + OFF_P);
    __nv_bfloat16* pL = (__nv_bfloat16*)(smc + OFF_P + PSTRIDE);
    float* stg  = (float*)(smc + OFF_P);
    float* sW   = (float*)(smc + OFF_W);
    float* sInv = (float*)(smc + OFF_I);
    float* sSum = (float*)(smc + OFF_SU);

    const int tid = threadIdx.x;
    const int warp = tid >> 5, lane = tid & 31;
    const int g = lane >> 2, t = lane & 3;
    const int nq = SS / 32;
    const int qt = blockIdx.x % nq;
    const int h  = (blockIdx.x / nq) % HH;
    const int b  = blockIdx.x / (nq * HH);
    const int q0 = qt * 32;
    const int bh = b * HH + h;

    const int qrow = tid >> 4;        // sweep row ownership
    const int s16  = tid & 15;
    const int qg   = q0 + qrow;
    float* aout = attn_out + ((size_t)bh * SS + q0) * SS;

    // ---- load Q tile ----
    {
        int i = tid;
        int s = i >> 8, idx = i & 255;
        int row = idx >> 3, c = (idx & 7) * 8;
        const __nv_bfloat16* src = s ? QsL : QsH;
        __nv_bfloat16* dst = s ? qL : qH;
        *(uint4*)&dst[row * KP + c] =
            *(const uint4*)&src[((size_t)(b * SS) + q0 + row) * DD + h * DH + c];
    }
    // ---- load embK into region A ----
    for (int i = tid; i < 1088; i += 512) {
        int r = i >> 3, c = (i & 7) * 8;
        float v[8] = {};
        if (r < RR) {
            float4 x = *(const float4*)&embK[(size_t)r * DD + h * DH + c];
            float4 y = *(const float4*)&embK[(size_t)r * DD + h * DH + c + 4];
            v[0]=x.x; v[1]=x.y; v[2]=x.z; v[3]=x.w; v[4]=y.x; v[5]=y.y; v[6]=y.z; v[7]=y.w;
        }
        #pragma unroll
        for (int j = 0; j < 8; j++) {
            __nv_bfloat16 hb = __float2bfloat16(v[j]);
            aH[r * KP + c + j] = hb;
            aL[r * KP + c + j] = __float2bfloat16(v[j] - __bfloat162float(hb));
        }
    }
    __syncthreads();

    // ---- rel table: sW[q][r] = Q . embK_r ----
    for (int nt = warp; nt < 17; nt += 16) {
        float dr[2][4] = {};
        #pragma unroll
        for (int ks = 0; ks < 4; ks++) {
            int kk = ks * 16 + 2 * t;
            int rb = (nt * 8 + g) * KP;
            uint32_t bh2[2] = {*(uint32_t*)&aH[rb + kk], *(uint32_t*)&aH[rb + kk + 8]};
            uint32_t bl2[2] = {*(uint32_t*)&aL[rb + kk], *(uint32_t*)&aL[rb + kk + 8]};
            #pragma unroll
            for (int mi = 0; mi < 2; mi++) {
                int r0 = (mi * 16 + g) * KP, r1 = r0 + 8 * KP;
                uint32_t ah4[4] = {*(uint32_t*)&qH[r0 + kk], *(uint32_t*)&qH[r1 + kk],
                                   *(uint32_t*)&qH[r0 + kk + 8], *(uint32_t*)&qH[r1 + kk + 8]};
                uint32_t al4[4] = {*(uint32_t*)&qL[r0 + kk], *(uint32_t*)&qL[r1 + kk],
                                   *(uint32_t*)&qL[r0 + kk + 8], *(uint32_t*)&qL[r1 + kk + 8]};
                mma16816(dr[mi], ah4, bh2);
                mma16816(dr[mi], ah4, bl2);
                mma16816(dr[mi], al4, bh2);
            }
        }
        #pragma unroll
        for (int mi = 0; mi < 2; mi++) {
            int q = mi * 16 + g;
            int r = nt * 8 + 2 * t;
            if (r < RR)     sW[q * WP + r]           = dr[mi][0];
            if (r + 1 < RR) sW[q * WP + r + 1]       = dr[mi][1];
            if (r < RR)     sW[(q + 8) * WP + r]     = dr[mi][2];
            if (r + 1 < RR) sW[(q + 8) * WP + r + 1] = dr[mi][3];
        }
    }

    const float scale = 0.125f;
    const int wn = warp >> 2, hf = warp & 3;   // PV warp shape
    float oacc[2][2][4] = {};
    float sumacc = 0.f, s0acc = 0.f;

    // ---- streaming chunks: scores -> exp/convert -> PV ----
    for (int kt = 0; kt < 8; kt++) {
        // load K chunk (region A) -- previous PV (V reads) done at loop-top barrier
        __syncthreads();
        {
            size_t base = ((size_t)(b * SS) + kt * 128) * DD + h * DH;
            #pragma unroll
            for (int it = 0; it < 4; it++) {
                int i = tid + it * 512;
                int s = i >> 10, idx = i & 1023;
                int row = idx >> 3, c = (idx & 7) * 8;
                const __nv_bfloat16* src = s ? KsL : KsH;
                CP_ASYNC16(sb + OFF_A + s * ASTRIDE + (uint32_t)(row * KP + c) * 2,
                           &src[base + (size_t)row * DD + c]);
            }
            CP_COMMIT();
            CP_WAIT0();
        }
        __syncthreads();

        // score MMA: warp covers chunk cols warp*8..warp*8+7
        float dacc[2][4] = {};
        #pragma unroll
        for (int ks = 0; ks < 4; ks++) {
            int kk = ks * 16 + 2 * t;
            int rb = (warp * 8 + g) * KP;
            uint32_t bh2[2] = {*(uint32_t*)&aH[rb + kk], *(uint32_t*)&aH[rb + kk + 8]};
            uint32_t bl2[2] = {*(uint32_t*)&aL[rb + kk], *(uint32_t*)&aL[rb + kk + 8]};
            #pragma unroll
            for (int mi = 0; mi < 2; mi++) {
                int r0 = (mi * 16 + g) * KP, r1 = r0 + 8 * KP;
                uint32_t ah4[4] = {*(uint32_t*)&qH[r0 + kk], *(uint32_t*)&qH[r1 + kk],
                                   *(uint32_t*)&qH[r0 + kk + 8], *(uint32_t*)&qH[r1 + kk + 8]};
                uint32_t al4[4] = {*(uint32_t*)&qL[r0 + kk], *(uint32_t*)&qL[r1 + kk],
                                   *(uint32_t*)&qL[r0 + kk + 8], *(uint32_t*)&qL[r1 + kk + 8]};
                mma16816(dacc[mi], ah4, bh2);
                mma16816(dacc[mi], ah4, bl2);
                mma16816(dacc[mi], al4, bh2);
            }
        }
        #pragma unroll
        for (int mi = 0; mi < 2; mi++) {
            int q = mi * 16 + g;
            int ck = warp * 8 + 2 * t;
            int gk = kt * 128 + ck;
            #pragma unroll
            for (int rr = 0; rr < 2; rr++) {
                int qq = q + rr * 8;
                int qgl = q0 + qq;
                int rel0 = min(max(gk - qgl,     -KWIN), KWIN) + KWIN;
                int rel1 = min(max(gk + 1 - qgl, -KWIN), KWIN) + KWIN;
                sSc[qq * SCP + ck]     = (dacc[mi][rr * 2]     + sW[qq * WP + rel0]) * scale;
                sSc[qq * SCP + ck + 1] = (dacc[mi][rr * 2 + 1] + sW[qq * WP + rel1]) * scale;
            }
        }
        __syncthreads();

        // V chunk load (async) overlapped with sweep
        {
            #pragma unroll
            for (int it = 0; it < 4; it++) {
                int i = tid + it * 512;
                int s = i >> 10, idx = i & 1023;
                int d = idx >> 4, g4 = (idx & 15) * 4;
                const uint32_t* src = s ? vtL : vtH;
                CP_ASYNC16(sb + OFF_A + s * ASTRIDE + (uint32_t)(d * VP + g4) * 4,
                           &src[((size_t)bh * DH + d) * (SS / 2) + kt * 64 + g4]);
            }
            CP_COMMIT();
        }

        // sweep: exp, attn write (unnormalized), P convert, sum/tail accumulate
        {
            int c0 = s16 * 8;
            int gk0 = kt * 128 + c0;
            float e[8];
            float4 x = *(float4*)&sSc[qrow * SCP + c0];
            float4 y = *(float4*)&sSc[qrow * SCP + c0 + 4];
            e[0]=__expf(x.x); e[1]=__expf(x.y); e[2]=__expf(x.z); e[3]=__expf(x.w);
            e[4]=__expf(y.x); e[5]=__expf(y.y); e[6]=__expf(y.z); e[7]=__expf(y.w);
            #pragma unroll
            for (int j = 0; j < 8; j++) {
                sumacc += e[j];
                if (gk0 + j <= qg - KWIN) s0acc += e[j];
            }
            *(float4*)&aout[(size_t)qrow * SS + gk0]     = make_float4(e[0], e[1], e[2], e[3]);
            *(float4*)&aout[(size_t)qrow * SS + gk0 + 4] = make_float4(e[4], e[5], e[6], e[7]);
            #pragma unroll
            for (int p = 0; p < 4; p++) {
                uint32_t hpk, lpk;
                asm("cvt.rn.bf16x2.f32 %0, %1, %2;" : "=r"(hpk) : "f"(e[2*p+1]), "f"(e[2*p]));
                float h0 = __uint_as_float(hpk << 16);
                float h1 = __uint_as_float(hpk & 0xffff0000u);
                asm("cvt.rn.bf16x2.f32 %0, %1, %2;" : "=r"(lpk) : "f"(e[2*p+1] - h1), "f"(e[2*p] - h0));
                *(uint32_t*)&pH[qrow * PP + c0 + 2*p] = hpk;
                *(uint32_t*)&pL[qrow * PP + c0 + 2*p] = lpk;
            }
        }
        CP_WAIT0();
        __syncthreads();

        // PV MMA: wn = 16 d-cols, hf = 32 chunk-cols
        #pragma unroll
        for (int ks = 0; ks < 2; ks++) {
            int kb = hf * 32 + ks * 16 + 2 * t;
            int widx = hf * 16 + ks * 8 + t;
            uint32_t bh2[2][2], bl2[2][2];
            #pragma unroll
            for (int ni = 0; ni < 2; ni++) {
                int vrow = (wn * 16 + ni * 8 + g) * VP;
                bh2[ni][0] = vH[vrow + widx];  bh2[ni][1] = vH[vrow + widx + 4];
                bl2[ni][0] = vL[vrow + widx];  bl2[ni][1] = vL[vrow + widx + 4];
            }
            #pragma unroll
            for (int mi = 0; mi < 2; mi++) {
                int r0 = (mi * 16 + g) * PP, r1 = r0 + 8 * PP;
                uint32_t ah4[4] = {*(uint32_t*)&pH[r0 + kb], *(uint32_t*)&pH[r1 + kb],
                                   *(uint32_t*)&pH[r0 + kb + 8], *(uint32_t*)&pH[r1 + kb + 8]};
                uint32_t al4[4] = {*(uint32_t*)&pL[r0 + kb], *(uint32_t*)&pL[r1 + kb],
                                   *(uint32_t*)&pL[r0 + kb + 8], *(uint32_t*)&pL[r1 + kb + 8]};
                #pragma unroll
                for (int ni = 0; ni < 2; ni++) {
                    mma16816(oacc[mi][ni], ah4, bh2[ni]);
                    mma16816(oacc[mi][ni], ah4, bl2[ni]);
                    mma16816(oacc[mi][ni], al4, bh2[ni]);
                }
            }
        }
    }
    __syncthreads();

    // ---- reduce sums; rel table in sW is dead now ----
    {
        float sum = sumacc, s0 = s0acc;
        #pragma unroll
        for (int off = 1; off < 16; off <<= 1) {
            sum += __shfl_xor_sync(0xffffffffu, sum, off, 16);
            s0  += __shfl_xor_sync(0xffffffffu, s0,  off, 16);
        }
        if (s16 == 0) {
            sSum[qrow] = sum;
            sInv[qrow] = 1.f / sum;
            sW[qrow * WP + 0] = s0;
        }
    }
    __syncthreads();

    // ---- w buckets: middle from gmem readback, s1 derived ----
    {
        float mid = 0.f;
        for (int r = 1 + s16; r <= 127; r += 16) {
            int k = qg - KWIN + r;
            float v = (k >= 0 && k < SS) ? aout[(size_t)qrow * SS + k] : 0.f;
            sW[qrow * WP + r] = v;
            mid += v;
        }
        #pragma unroll
        for (int off = 1; off < 16; off <<= 1)
            mid += __shfl_xor_sync(0xffffffffu, mid, off, 16);
        if (s16 == 0)
            sW[qrow * WP + 128] = sSum[qrow] - sW[qrow * WP + 0] - mid;
        for (int i = tid; i < 32 * 31; i += 512) {
            int q = i / 31, r = 129 + (i % 31);
            sW[q * WP + r] = 0.f;
        }
    }
    __syncthreads();

    // ---- extra chunk: w @ embV_h (hf 0,1; 2x80 cols) ----
    {
        for (int i = tid; i < 640; i += 512) {
            int p = i >> 3, dg = i & 7;
            int r0 = 2 * p, r1 = 2 * p + 1;
            float v0[8] = {}, v1[8] = {};
            if (r0 < RR) {
                float4 x = *(const float4*)&embV[(size_t)r0 * DD + h * DH + dg * 8];
                float4 y = *(const float4*)&embV[(size_t)r0 * DD + h * DH + dg * 8 + 4];
                v0[0]=x.x; v0[1]=x.y; v0[2]=x.z; v0[3]=x.w; v0[4]=y.x; v0[5]=y.y; v0[6]=y.z; v0[7]=y.w;
            }
            if (r1 < RR) {
                float4 x = *(const float4*)&embV[(size_t)r1 * DD + h * DH + dg * 8];
                float4 y = *(const float4*)&embV[(size_t)r1 * DD + h * DH + dg * 8 + 4];
                v1[0]=x.x; v1[1]=x.y; v1[2]=x.z; v1[3]=x.w; v1[4]=y.x; v1[5]=y.y; v1[6]=y.z; v1[7]=y.w;
            }
            #pragma unroll
            for (int j = 0; j < 8; j++) {
                __nv_bfloat16 h0 = __float2bfloat16(v0[j]);
                __nv_bfloat16 h1 = __float2bfloat16(v1[j]);
                __nv_bfloat16 l0 = __float2bfloat16(v0[j] - __bfloat162float(h0));
                __nv_bfloat16 l1 = __float2bfloat16(v1[j] - __bfloat162float(h1));
                vH[(dg * 8 + j) * VP + p] =
                    (uint32_t)__bfloat16_as_ushort(h0) | ((uint32_t)__bfloat16_as_ushort(h1) << 16);
                vL[(dg * 8 + j) * VP + p] =
                    (uint32_t)__bfloat16_as_ushort(l0) | ((uint32_t)__bfloat16_as_ushort(l1) << 16);
            }
        }
        for (int i = tid; i < 2560; i += 512) {
            int q = i / 80, c2 = (i % 80) * 2;
            float2 v = *(float2*)&sW[q * WP + c2];
            uint32_t hpk, lpk;
            asm("cvt.rn.bf16x2.f32 %0, %1, %2;" : "=r"(hpk) : "f"(v.y), "f"(v.x));
            float h0 = __uint_as_float(hpk << 16);
            float h1 = __uint_as_float(hpk & 0xffff0000u);
            asm("cvt.rn.bf16x2.f32 %0, %1, %2;" : "=r"(lpk) : "f"(v.y - h1), "f"(v.x - h0));
            *(uint32_t*)&pH[q * PP + c2] = hpk;
            *(uint32_t*)&pL[q * PP + c2] = lpk;
        }
        __syncthreads();

        if (hf < 2) {
            #pragma unroll
            for (int ks = 0; ks < 5; ks++) {
                int kb = hf * 80 + ks * 16 + 2 * t;
                int widx = hf * 40 + ks * 8 + t;
                uint32_t bh2[2][2], bl2[2][2];
                #pragma unroll
                for (int ni = 0; ni < 2; ni++) {
                    int vrow = (wn * 16 + ni * 8 + g) * VP;
                    bh2[ni][0] = vH[vrow + widx];  bh2[ni][1] = vH[vrow + widx + 4];
                    bl2[ni][0] = vL[vrow + widx];  bl2[ni][1] = vL[vrow + widx + 4];
                }
                #pragma unroll
                for (int mi = 0; mi < 2; mi++) {
                    int r0 = (mi * 16 + g) * PP, r1 = r0 + 8 * PP;
                    uint32_t ah4[4] = {*(uint32_t*)&pH[r0 + kb], *(uint32_t*)&pH[r1 + kb],
                                       *(uint32_t*)&pH[r0 + kb + 8], *(uint32_t*)&pH[r1 + kb + 8]};
                    uint32_t al4[4] = {*(uint32_t*)&pL[r0 + kb], *(uint32_t*)&pL[r1 + kb],
                                       *(uint32_t*)&pL[r0 + kb + 8], *(uint32_t*)&pL[r1 + kb + 8]};
                    #pragma unroll
                    for (int ni = 0; ni < 2; ni++) {
                        mma16816(oacc[mi][ni], ah4, bh2[ni]);
                        mma16816(oacc[mi][ni], ah4, bl2[ni]);
                        mma16816(oacc[mi][ni], al4, bh2[ni]);
                    }
                }
            }
        }
        __syncthreads();
    }

    // ---- reduce 4 hf partials (two rounds, staging in pH/pL region) ----
    {
        if (hf & 1) {
            int slot = hf >> 1;
            #pragma unroll
            for (int mi = 0; mi < 2; mi++)
                #pragma unroll
                for (int ni = 0; ni < 2; ni++) {
                    int q = mi * 16 + g, dc = wn * 16 + ni * 8 + 2 * t;
                    stg[slot * 2048 + q * 64 + dc]           = oacc[mi][ni][0];
                    stg[slot * 2048 + q * 64 + dc + 1]       = oacc[mi][ni][1];
                    stg[slot * 2048 + (q + 8) * 64 + dc]     = oacc[mi][ni][2];
                    stg[slot * 2048 + (q + 8) * 64 + dc + 1] = oacc[mi][ni][3];
                }
        }
        __syncthreads();
        if (!(hf & 1)) {
            int slot = hf >> 1;
            #pragma unroll
            for (int mi = 0; mi < 2; mi++)
                #pragma unroll
                for (int ni = 0; ni < 2; ni++) {
                    int q = mi * 16 + g, dc = wn * 16 + ni * 8 + 2 * t;
                    oacc[mi][ni][0] += stg[slot * 2048 + q * 64 + dc];
                    oacc[mi][ni][1] += stg[slot * 2048 + q * 64 + dc + 1];
                    oacc[mi][ni][2] += stg[slot * 2048 + (q + 8) * 64 + dc];
                    oacc[mi][ni][3] += stg[slot * 2048 + (q + 8) * 64 + dc + 1];
                }
        }
        __syncthreads();
        if (hf == 2) {
            #pragma unroll
            for (int mi = 0; mi < 2; mi++)
                #pragma unroll
                for (int ni = 0; ni < 2; ni++) {
                    int q = mi * 16 + g, dc = wn * 16 + ni * 8 + 2 * t;
                    stg[q * 64 + dc]           = oacc[mi][ni][0];
                    stg[q * 64 + dc + 1]       = oacc[mi][ni][1];
                    stg[(q + 8) * 64 + dc]     = oacc[mi][ni][2];
                    stg[(q + 8) * 64 + dc + 1] = oacc[mi][ni][3];
                }
        }
        __syncthreads();
        if (hf == 0) {
            #pragma unroll
            for (int mi = 0; mi < 2; mi++)
                #pragma unroll
                for (int ni = 0; ni < 2; ni++) {
                    int q = mi * 16 + g, dc = wn * 16 + ni * 8 + 2 * t;
                    float v00 = (oacc[mi][ni][0] + stg[q * 64 + dc])           * sInv[q];
                    float v01 = (oacc[mi][ni][1] + stg[q * 64 + dc + 1])       * sInv[q];
                    float v10 = (oacc[mi][ni][2] + stg[(q + 8) * 64 + dc])     * sInv[q + 8];
                    float v11 = (oacc[mi][ni][3] + stg[(q + 8) * 64 + dc + 1]) * sInv[q + 8];
                    uint32_t hp0, lp0, hp1, lp1;
                    asm("cvt.rn.bf16x2.f32 %0, %1, %2;" : "=r"(hp0) : "f"(v01), "f"(v00));
                    asm("cvt.rn.bf16x2.f32 %0, %1, %2;" : "=r"(hp1) : "f"(v11), "f"(v10));
                    float h00 = __uint_as_float(hp0 << 16);
                    float h01 = __uint_as_float(hp0 & 0xffff0000u);
                    float h10 = __uint_as_float(hp1 << 16);
                    float h11 = __uint_as_float(hp1 & 0xffff0000u);
                    asm("cvt.rn.bf16x2.f32 %0, %1, %2;" : "=r"(lp0) : "f"(v01 - h01), "f"(v00 - h00));
                    asm("cvt.rn.bf16x2.f32 %0, %1, %2;" : "=r"(lp1) : "f"(v11 - h11), "f"(v10 - h10));
                    size_t d0 = ((size_t)(b * SS) + q0 + q) * DD + h * DH + dc;
                    size_t d1 = ((size_t)(b * SS) + q0 + q + 8) * DD + h * DH + dc;
                    *(uint32_t*)&ctxH[d0] = hp0;
                    *(uint32_t*)&ctxL[d0] = lp0;
                    *(uint32_t*)&ctxH[d1] = hp1;
                    *(uint32_t*)&ctxL[d1] = lp1;
                }
        }
    }

    // ---- normalize attn in place ----
    for (int i = tid; i < 8192; i += 512) {
        int qq = i >> 8, k4 = (i & 255) * 4;
        float4 v = *(float4*)&aout[(size_t)qq * SS + k4];
        float s = sInv[qq];
        v.x *= s; v.y *= s; v.z *= s; v.w *= s;
        *(float4*)&aout[(size_t)qq * SS + k4] = v;
    }
}

// ---------------- launch ----------------
extern "C" void kernel_launch(void* const* d_in, const int* in_sizes, int n_in,
                              void* d_out, int out_size)
{
    const float* query = (const float*)d_in[0];
    const float* key   = (const float*)d_in[1];
    const float* value = (const float*)d_in[2];
    const float* WQ_w  = (const float*)d_in[3];
    const float* WQ_b  = (const float*)d_in[4];
    const float* WK_w  = (const float*)d_in[5];
    const float* WK_b  = (const float*)d_in[6];
    const float* WV_w  = (const float*)d_in[7];
    const float* WV_b  = (const float*)d_in[8];
    const float* WO_w  = (const float*)d_in[9];
    const float* WO_b  = (const float*)d_in[10];
    const float* embK  = (const float*)d_in[11];
    const float* embV  = (const float*)d_in[12];

    float* out = (float*)d_out;                       // [B,S,D]
    float* attn = out + (size_t)BB * SS * DD;         // [B,H,S,S]

    static float *Qp = nullptr, *Kp, *Vp;
    static __nv_bfloat16 *qh, *ql, *kh, *kl, *vh, *vl, *ch, *cl;
    static __nv_bfloat16 *wqh, *wql, *wkh, *wkl, *wvh, *wvl, *woh, *wol;
    static uint32_t *vtH, *vtL;
    if (!Qp) {
        cudaGetSymbolAddress((void**)&Qp, g_Qp);
        cudaGetSymbolAddress((void**)&Kp, g_Kp);
        cudaGetSymbolAddress((void**)&Vp, g_Vp);
        cudaGetSymbolAddress((void**)&qh, g_qh);   cudaGetSymbolAddress((void**)&ql, g_ql);
        cudaGetSymbolAddress((void**)&kh, g_kh);   cudaGetSymbolAddress((void**)&kl, g_kl);
        cudaGetSymbolAddress((void**)&vh, g_vh);   cudaGetSymbolAddress((void**)&vl, g_vl);
        cudaGetSymbolAddress((void**)&ch, g_ch);   cudaGetSymbolAddress((void**)&cl, g_cl);
        cudaGetSymbolAddress((void**)&wqh, g_wqh); cudaGetSymbolAddress((void**)&wql, g_wql);
        cudaGetSymbolAddress((void**)&wkh, g_wkh); cudaGetSymbolAddress((void**)&wkl, g_wkl);
        cudaGetSymbolAddress((void**)&wvh, g_wvh); cudaGetSymbolAddress((void**)&wvl, g_wvl);
        cudaGetSymbolAddress((void**)&woh, g_woh); cudaGetSymbolAddress((void**)&wol, g_wol);
        cudaGetSymbolAddress((void**)&vtH, g_vtH); cudaGetSymbolAddress((void**)&vtL, g_vtL);
        cudaFuncSetAttribute(attn_mma,
                             cudaFuncAttributeMaxDynamicSharedMemorySize, ASM_BYTES);
        cudaFuncSetAttribute(gemm_qkv,
                             cudaFuncAttributeMaxDynamicSharedMemorySize, GSMB);
        cudaFuncSetAttribute(gemm_o,
                             cudaFuncAttributeMaxDynamicSharedMemorySize, GSMB);
    }

    __nv_bfloat16* QsH = (__nv_bfloat16*)Qp;  __nv_bfloat16* QsL = QsH + (size_t)MTOT * DD;
    __nv_bfloat16* KsH = (__nv_bfloat16*)Kp;  __nv_bfloat16* KsL = KsH + (size_t)MTOT * DD;
    __nv_bfloat16* VsH = (__nv_bfloat16*)Vp;  __nv_bfloat16* VsL = VsH + (size_t)MTOT * DD;

    const int NIN = MTOT * DD;
    const int NW  = DD * DD;

    split_all_kernel<<<dim3(NIN / 4 / 256, 7), 256>>>(
        query, qh, ql, key, kh, kl, value, vh, vl,
        WQ_w, wqh, wql, WK_w, wkh, wkl, WV_w, wvh, wvl, WO_w, woh, wol,
        NIN, NW);
    gemm_qkv<<<dim3(DD / 128, MTOT / 64, 3), 256, GSMB>>>(
        qh, ql, wqh, wql, WQ_b, QsH, QsL,
        kh, kl, wkh, wkl, WK_b, KsH, KsL,
        vh, vl, wvh, wvl, WV_b, VsH, VsL);
    vtrans_kernel<<<BB * HH * 8, 256>>>(VsH, VsL, vtH, vtL);
    attn_mma<<<BB * HH * (SS / 32), 512, ASM_BYTES>>>(
        QsH, QsL, KsH, KsL, vtH, vtL, embK, embV, attn, ch, cl);
    gemm_o<<<dim3(DD / 128, MTOT / 64), 256, GSMB>>>(ch, cl, woh, wol, WO_b, out);
}

// round 17
// speedup vs baseline: 1.4704x; 1.4704x over previous
#include <cuda_runtime.h>
#include <cuda_bf16.h>
#include <cstdint>
#include <cstring>

// Problem constants
#define BB 4
#define SS 1024
#define DD 768
#define HH 12
#define DH 64
#define RR 129          // 2K+1, K=64
#define KWIN 64

#define MTOT (BB * SS)  // 4096

// ---------------- scratch (no allocation allowed) ----------------
__device__ float g_Qp[MTOT * DD];      // reinterpreted: bf16 QsH/QsL
__device__ float g_Kp[MTOT * DD];      // reinterpreted: bf16 KsH/KsL
__device__ float g_Vp[MTOT * DD];      // reinterpreted: bf16 VsH/VsL

__device__ __nv_bfloat16 g_qh[MTOT * DD],  g_ql[MTOT * DD];
__device__ __nv_bfloat16 g_kh[MTOT * DD],  g_kl[MTOT * DD];
__device__ __nv_bfloat16 g_vh[MTOT * DD],  g_vl[MTOT * DD];
__device__ __nv_bfloat16 g_ch[MTOT * DD],  g_cl[MTOT * DD];
__device__ __nv_bfloat16 g_wqh[DD * DD], g_wql[DD * DD];
__device__ __nv_bfloat16 g_wkh[DD * DD], g_wkl[DD * DD];
__device__ __nv_bfloat16 g_wvh[DD * DD], g_wvl[DD * DD];
__device__ __nv_bfloat16 g_woh[DD * DD], g_wol[DD * DD];

// packed V^T: [b*HH+h][d(64)][pair(512)]
__device__ uint32_t g_vtH[BB * HH * DH * (SS / 2)];
__device__ uint32_t g_vtL[BB * HH * DH * (SS / 2)];

// ---------------- cp.async helpers ----------------
__device__ __forceinline__ uint32_t smem_u32(const void* p) {
    uint32_t a;
    asm("{ .reg .u64 t; cvta.to.shared.u64 t, %1; cvt.u32.u64 %0, t; }"
        : "=r"(a) : "l"(p));
    return a;
}
#define CP_ASYNC16(sa, ga) \
    asm volatile("cp.async.cg.shared.global [%0], [%1], 16;" :: "r"(sa), "l"(ga))
#define CP_COMMIT() asm volatile("cp.async.commit_group;" ::: "memory")
#define CP_WAIT1()  asm volatile("cp.async.wait_group 1;" ::: "memory")
#define CP_WAIT0()  asm volatile("cp.async.wait_group 0;" ::: "memory")

// ---------------- fp32 -> bf16 hi/lo split ----------------
__device__ __forceinline__ void split4(const float* __restrict__ x,
                                       __nv_bfloat16* __restrict__ hi,
                                       __nv_bfloat16* __restrict__ lo, int i)
{
    float4 v = *(const float4*)&x[i];
    float vv[4] = {v.x, v.y, v.z, v.w};
    uint16_t h[4], l[4];
    #pragma unroll
    for (int p = 0; p < 4; p++) {
        __nv_bfloat16 hb = __float2bfloat16(vv[p]);
        __nv_bfloat16 lb = __float2bfloat16(vv[p] - __bfloat162float(hb));
        h[p] = __bfloat16_as_ushort(hb);
        l[p] = __bfloat16_as_ushort(lb);
    }
    *(uint2*)&hi[i] = make_uint2(((uint32_t)h[1] << 16) | h[0], ((uint32_t)h[3] << 16) | h[2]);
    *(uint2*)&lo[i] = make_uint2(((uint32_t)l[1] << 16) | l[0], ((uint32_t)l[3] << 16) | l[2]);
}

__global__ __launch_bounds__(256) void split_all_kernel(
    const float* __restrict__ i0, __nv_bfloat16* i0h, __nv_bfloat16* i0l,
    const float* __restrict__ i1, __nv_bfloat16* i1h, __nv_bfloat16* i1l,
    const float* __restrict__ i2, __nv_bfloat16* i2h, __nv_bfloat16* i2l,
    const float* __restrict__ w0, __nv_bfloat16* w0h, __nv_bfloat16* w0l,
    const float* __restrict__ w1, __nv_bfloat16* w1h, __nv_bfloat16* w1l,
    const float* __restrict__ w2, __nv_bfloat16* w2h, __nv_bfloat16* w2l,
    const float* __restrict__ w3, __nv_bfloat16* w3h, __nv_bfloat16* w3l,
    int nin, int nw)
{
    int i = (blockIdx.x * 256 + threadIdx.x) * 4;
    int y = blockIdx.y;
    int n = (y < 3) ? nin : nw;
    if (i >= n) return;
    const float* x; __nv_bfloat16 *hi, *lo;
    switch (y) {
        case 0: x = i0; hi = i0h; lo = i0l; break;
        case 1: x = i1; hi = i1h; lo = i1l; break;
        case 2: x = i2; hi = i2h; lo = i2l; break;
        case 3: x = w0; hi = w0h; lo = w0l; break;
        case 4: x = w1; hi = w1h; lo = w1l; break;
        case 5: x = w2; hi = w2h; lo = w2l; break;
        default: x = w3; hi = w3h; lo = w3l; break;
    }
    split4(x, hi, lo, i);
}

// ---------------- mma.sync helper ----------------
__device__ __forceinline__ void mma16816(float* d, const uint32_t* a, const uint32_t* b) {
    asm volatile("mma.sync.aligned.m16n8k16.row.col.f32.bf16.bf16.f32 "
        "{%0,%1,%2,%3}, {%4,%5,%6,%7}, {%8,%9}, {%0,%1,%2,%3};"
        : "+f"(d[0]), "+f"(d[1]), "+f"(d[2]), "+f"(d[3])
        : "r"(a[0]), "r"(a[1]), "r"(a[2]), "r"(a[3]), "r"(b[0]), "r"(b[1]));
}

// ---------------- bf16-split GEMM, 64x128 tile, cp.async 2-stage ----------------
#define SP 40
#define AARR 5120
#define WARR 10240
#define GBUF 30720
#define GSMB (2 * GBUF)

__device__ __forceinline__ void gemm_issue64(
    uint32_t sb, int buf, int tid, int bm, int bn, int k0, int Kd,
    const __nv_bfloat16* __restrict__ Ah, const __nv_bfloat16* __restrict__ Al,
    const __nv_bfloat16* __restrict__ Wh, const __nv_bfloat16* __restrict__ Wl)
{
    uint32_t bo = sb + buf * GBUF;
    {
        int rowA = tid >> 2, cc = (tid & 3) * 8;
        size_t ga = (size_t)(bm + rowA) * Kd + k0 + cc;
        uint32_t so = (uint32_t)(rowA * SP + cc) * 2;
        CP_ASYNC16(bo + so,        Ah + ga);
        CP_ASYNC16(bo + AARR + so, Al + ga);
    }
    #pragma unroll
    for (int it = 0; it < 2; it++) {
        int i = tid + it * 256;
        int rowW = i >> 2, cc = (i & 3) * 8;
        size_t gw = (size_t)(bn + rowW) * Kd + k0 + cc;
        uint32_t so = (uint32_t)(rowW * SP + cc) * 2;
        CP_ASYNC16(bo + 2 * AARR + so,        Wh + gw);
        CP_ASYNC16(bo + 2 * AARR + WARR + so, Wl + gw);
    }
    CP_COMMIT();
}

__device__ __forceinline__ void gemm_body64(
    const __nv_bfloat16* __restrict__ Ah, const __nv_bfloat16* __restrict__ Al,
    const __nv_bfloat16* __restrict__ Wh, const __nv_bfloat16* __restrict__ Wl,
    const float* __restrict__ bias, float* __restrict__ C,
    __nv_bfloat16* __restrict__ Ch, __nv_bfloat16* __restrict__ Cl,
    int M, int N, int Kd)
{
    extern __shared__ char gsm[];
    uint32_t sb = smem_u32(gsm);

    const int tid = threadIdx.x;
    const int bm = blockIdx.y * 64, bn = blockIdx.x * 128;
    const int warp = tid >> 5, lane = tid & 31;
    const int wm = warp & 1, wn = warp >> 1;
    const int g = lane >> 2, t = lane & 3;

    float d[2][4][4] = {};

    const int nch = Kd / 32;
    gemm_issue64(sb, 0, tid, bm, bn, 0, Kd, Ah, Al, Wh, Wl);

    for (int c = 0; c < nch; c++) {
        if (c + 1 < nch) {
            gemm_issue64(sb, (c + 1) & 1, tid, bm, bn, (c + 1) * 32, Kd, Ah, Al, Wh, Wl);
            CP_WAIT1();
        } else {
            CP_WAIT0();
        }
        __syncthreads();

        const char* st = gsm + (c & 1) * GBUF;
        const __nv_bfloat16* sAh = (const __nv_bfloat16*)st;
        const __nv_bfloat16* sAl = (const __nv_bfloat16*)(st + AARR);
        const __nv_bfloat16* sWh = (const __nv_bfloat16*)(st + 2 * AARR);
        const __nv_bfloat16* sWl = (const __nv_bfloat16*)(st + 2 * AARR + WARR);

        #pragma unroll
        for (int ks = 0; ks < 2; ks++) {
            const int kk = ks * 16 + 2 * t;
            uint32_t bh[4][2], bl[4][2];
            #pragma unroll
            for (int ni = 0; ni < 4; ni++) {
                int rb = (wn * 32 + ni * 8 + g) * SP;
                bh[ni][0] = *(const uint32_t*)&sWh[rb + kk];
                bh[ni][1] = *(const uint32_t*)&sWh[rb + kk + 8];
                bl[ni][0] = *(const uint32_t*)&sWl[rb + kk];
                bl[ni][1] = *(const uint32_t*)&sWl[rb + kk + 8];
            }
            #pragma unroll
            for (int mi = 0; mi < 2; mi++) {
                int r0 = (wm * 32 + mi * 16 + g) * SP;
                int r1 = r0 + 8 * SP;
                uint32_t ah[4], al[4];
                ah[0] = *(const uint32_t*)&sAh[r0 + kk];
                ah[1] = *(const uint32_t*)&sAh[r1 + kk];
                ah[2] = *(const uint32_t*)&sAh[r0 + kk + 8];
                ah[3] = *(const uint32_t*)&sAh[r1 + kk + 8];
                al[0] = *(const uint32_t*)&sAl[r0 + kk];
                al[1] = *(const uint32_t*)&sAl[r1 + kk];
                al[2] = *(const uint32_t*)&sAl[r0 + kk + 8];
                al[3] = *(const uint32_t*)&sAl[r1 + kk + 8];
                #pragma unroll
                for (int ni = 0; ni < 4; ni++) {
                    mma16816(d[mi][ni], ah, bh[ni]);
                    mma16816(d[mi][ni], ah, bl[ni]);
                    mma16816(d[mi][ni], al, bh[ni]);
                }
            }
        }
        __syncthreads();
    }

    #pragma unroll
    for (int mi = 0; mi < 2; mi++) {
        int r0 = bm + wm * 32 + mi * 16 + g;
        #pragma unroll
        for (int ni = 0; ni < 4; ni++) {
            int c0 = bn + wn * 32 + ni * 8 + 2 * t;
            float b0 = bias[c0], b1 = bias[c0 + 1];
            float v00 = d[mi][ni][0] + b0, v01 = d[mi][ni][1] + b1;
            float v10 = d[mi][ni][2] + b0, v11 = d[mi][ni][3] + b1;
            if (Ch) {
                uint32_t hp0, lp0, hp1, lp1;
                asm("cvt.rn.bf16x2.f32 %0, %1, %2;" : "=r"(hp0) : "f"(v01), "f"(v00));
                asm("cvt.rn.bf16x2.f32 %0, %1, %2;" : "=r"(hp1) : "f"(v11), "f"(v10));
                float h00 = __uint_as_float(hp0 << 16);
                float h01 = __uint_as_float(hp0 & 0xffff0000u);
                float h10 = __uint_as_float(hp1 << 16);
                float h11 = __uint_as_float(hp1 & 0xffff0000u);
                asm("cvt.rn.bf16x2.f32 %0, %1, %2;" : "=r"(lp0) : "f"(v01 - h01), "f"(v00 - h00));
                asm("cvt.rn.bf16x2.f32 %0, %1, %2;" : "=r"(lp1) : "f"(v11 - h11), "f"(v10 - h10));
                *(uint32_t*)&Ch[(size_t)r0 * N + c0]       = hp0;
                *(uint32_t*)&Cl[(size_t)r0 * N + c0]       = lp0;
                *(uint32_t*)&Ch[(size_t)(r0 + 8) * N + c0] = hp1;
                *(uint32_t*)&Cl[(size_t)(r0 + 8) * N + c0] = lp1;
            } else {
                C[(size_t)r0 * N + c0]           = v00;
                C[(size_t)r0 * N + c0 + 1]       = v01;
                C[(size_t)(r0 + 8) * N + c0]     = v10;
                C[(size_t)(r0 + 8) * N + c0 + 1] = v11;
            }
        }
    }
}

__global__ __launch_bounds__(256, 2) void gemm_qkv(
    const __nv_bfloat16* qh, const __nv_bfloat16* ql,
    const __nv_bfloat16* wqh, const __nv_bfloat16* wql, const float* WQb,
    __nv_bfloat16* QsH, __nv_bfloat16* QsL,
    const __nv_bfloat16* kh, const __nv_bfloat16* kl,
    const __nv_bfloat16* wkh, const __nv_bfloat16* wkl, const float* WKb,
    __nv_bfloat16* KsH, __nv_bfloat16* KsL,
    const __nv_bfloat16* vh, const __nv_bfloat16* vl,
    const __nv_bfloat16* wvh, const __nv_bfloat16* wvl, const float* WVb,
    __nv_bfloat16* VsH, __nv_bfloat16* VsL)
{
    if (blockIdx.z == 0)
        gemm_body64(qh, ql, wqh, wql, WQb, nullptr, QsH, QsL, MTOT, DD, DD);
    else if (blockIdx.z == 1)
        gemm_body64(kh, kl, wkh, wkl, WKb, nullptr, KsH, KsL, MTOT, DD, DD);
    else
        gemm_body64(vh, vl, wvh, wvl, WVb, nullptr, VsH, VsL, MTOT, DD, DD);
}

__global__ __launch_bounds__(256, 2) void gemm_o(
    const __nv_bfloat16* ch, const __nv_bfloat16* cl,
    const __nv_bfloat16* woh, const __nv_bfloat16* wol, const float* WOb,
    float* out)
{
    gemm_body64(ch, cl, woh, wol, WOb, out, nullptr, nullptr, MTOT, DD, DD);
}

// ---------------- V transpose+pack ----------------
__global__ __launch_bounds__(256) void vtrans_kernel(
    const __nv_bfloat16* __restrict__ VsH, const __nv_bfloat16* __restrict__ VsL,
    uint32_t* __restrict__ vtH, uint32_t* __restrict__ vtL)
{
    const int vt = blockIdx.x & 7;
    const int h  = (blockIdx.x >> 3) % HH;
    const int b  = blockIdx.x / (8 * HH);
    const int tid = threadIdx.x;
    const size_t obase = ((size_t)(b * HH + h)) * DH * (SS / 2) + vt * 64;

    for (int i = tid; i < 1024; i += 256) {
        int s = i >> 9, r = i & 511;
        int p = r >> 3, dg = r & 7;
        const __nv_bfloat16* src = s ? VsL : VsH;
        uint32_t* dst = s ? vtL : vtH;
        size_t base = ((size_t)(b * SS) + vt * 128 + 2 * p) * DD + h * DH + dg * 8;
        uint4 w0 = *(const uint4*)&src[base];
        uint4 w1 = *(const uint4*)&src[base + DD];
        uint16_t a0[8], a1[8];
        memcpy(a0, &w0, 16);
        memcpy(a1, &w1, 16);
        #pragma unroll
        for (int j = 0; j < 8; j++)
            dst[obase + (size_t)(dg * 8 + j) * (SS / 2) + p] =
                (uint32_t)a0[j] | ((uint32_t)a1[j] << 16);
    }
}

// ---------------- fused relative attention with mma.sync ----------------
#define KP 72
#define PP 168
#define VP 84
#define WP 160
#define SSTR 1040
#define OFF_A  0
#define ASTRIDE 21504
#define OFF_Q  43008
#define QSTRIDE 4608
#define OFF_P  52224
#define PSTRIDE 10752
#define OFF_W  73728
#define OFF_S  94208
#define OFF_I  227328
#define OFF_SU 227456
#define OFF_S0 227584
#define ASM_BYTES 227712

__global__ __launch_bounds__(512) void attn_mma(
    const __nv_bfloat16* __restrict__ QsH, const __nv_bfloat16* __restrict__ QsL,
    const __nv_bfloat16* __restrict__ KsH, const __nv_bfloat16* __restrict__ KsL,
    const uint32_t* __restrict__ vtH, const uint32_t* __restrict__ vtL,
    const float* __restrict__ embK, const float* __restrict__ embV,
    float* __restrict__ attn_out,
    __nv_bfloat16* __restrict__ ctxH, __nv_bfloat16* __restrict__ ctxL)
{
    extern __shared__ char smc[];
    __nv_bfloat16* aH = (__nv_bfloat16*)(smc + OFF_A);
    __nv_bfloat16* aL = (__nv_bfloat16*)(smc + OFF_A + ASTRIDE);
    uint32_t* vH = (uint32_t*)(smc + OFF_A);
    uint32_t* vL = (uint32_t*)(smc + OFF_A + ASTRIDE);
    __nv_bfloat16* qH = (__nv_bfloat16*)(smc + OFF_Q);
    __nv_bfloat16* qL = (__nv_bfloat16*)(smc + OFF_Q + QSTRIDE);
    __nv_bfloat16* pH = (__nv_bfloat16*)(smc + OFF_P);
    __nv_bfloat16* pL = (__nv_bfloat16*)(smc + OFF_P + PSTRIDE);
    float* stg  = (float*)(smc + OFF_P);
    float* sW   = (float*)(smc + OFF_W);
    float* sS   = (float*)(smc + OFF_S);
    float* sInv = (float*)(smc + OFF_I);
    float* sSum = (float*)(smc + OFF_SU);
    float* sS0  = (float*)(smc + OFF_S0);

    const int tid = threadIdx.x;
    const int warp = tid >> 5, lane = tid & 31;
    const int g = lane >> 2, t = lane & 3;
    const int nq = SS / 32;
    const int qt = blockIdx.x % nq;
    const int h  = (blockIdx.x / nq) % HH;
    const int b  = blockIdx.x / (nq * HH);
    const int q0 = qt * 32;
    const int bh = b * HH + h;

    // ---- load Q tile ----
    {
        int i = tid;
        if (i < 512) {
            int s = i >> 8, idx = i & 255;
            int row = idx >> 3, c = (idx & 7) * 8;
            const __nv_bfloat16* src = s ? QsL : QsH;
            __nv_bfloat16* dst = s ? qL : qH;
            *(uint4*)&dst[row * KP + c] =
                *(const uint4*)&src[((size_t)(b * SS) + q0 + row) * DD + h * DH + c];
        }
    }
    // ---- load embK ----
    for (int i = tid; i < 1088; i += 512) {
        int r = i >> 3, c = (i & 7) * 8;
        float v[8] = {};
        if (r < RR) {
            float4 x = *(const float4*)&embK[(size_t)r * DD + h * DH + c];
            float4 y = *(const float4*)&embK[(size_t)r * DD + h * DH + c + 4];
            v[0]=x.x; v[1]=x.y; v[2]=x.z; v[3]=x.w; v[4]=y.x; v[5]=y.y; v[6]=y.z; v[7]=y.w;
        }
        #pragma unroll
        for (int j = 0; j < 8; j++) {
            __nv_bfloat16 hb = __float2bfloat16(v[j]);
            aH[r * KP + c + j] = hb;
            aL[r * KP + c + j] = __float2bfloat16(v[j] - __bfloat162float(hb));
        }
    }
    if (tid < 32) { sSum[tid] = 0.f; sS0[tid] = 0.f; }
    __syncthreads();

    // ---- hoist Q-hi fragments to registers ----
    uint32_t qfh[4][2][4];
    #pragma unroll
    for (int ks = 0; ks < 4; ks++) {
        int kk = ks * 16 + 2 * t;
        #pragma unroll
        for (int mi = 0; mi < 2; mi++) {
            int r0 = (mi * 16 + g) * KP, r1 = r0 + 8 * KP;
            qfh[ks][mi][0] = *(uint32_t*)&qH[r0 + kk];
            qfh[ks][mi][1] = *(uint32_t*)&qH[r1 + kk];
            qfh[ks][mi][2] = *(uint32_t*)&qH[r0 + kk + 8];
            qfh[ks][mi][3] = *(uint32_t*)&qH[r1 + kk + 8];
        }
    }

    // prefetch K chunk 0
    uint4 kreg[4];
    #pragma unroll
    for (int it = 0; it < 4; it++) {
        int i = tid + it * 512;
        int s = i >> 10, idx = i & 1023;
        int row = idx >> 3, c = (idx & 7) * 8;
        const __nv_bfloat16* src = s ? KsL : KsH;
        kreg[it] = *(const uint4*)&src[((size_t)(b * SS) + row) * DD + h * DH + c];
    }

    // ---- rel table ----
    for (int nt = warp; nt < 17; nt += 16) {
        float dr[2][4] = {};
        #pragma unroll
        for (int ks = 0; ks < 4; ks++) {
            int kk = ks * 16 + 2 * t;
            int rb = (nt * 8 + g) * KP;
            uint32_t bh2[2] = {*(uint32_t*)&aH[rb + kk], *(uint32_t*)&aH[rb + kk + 8]};
            uint32_t bl2[2] = {*(uint32_t*)&aL[rb + kk], *(uint32_t*)&aL[rb + kk + 8]};
            #pragma unroll
            for (int mi = 0; mi < 2; mi++) {
                int r0 = (mi * 16 + g) * KP, r1 = r0 + 8 * KP;
                uint32_t al4[4] = {*(uint32_t*)&qL[r0 + kk], *(uint32_t*)&qL[r1 + kk],
                                   *(uint32_t*)&qL[r0 + kk + 8], *(uint32_t*)&qL[r1 + kk + 8]};
                mma16816(dr[mi], qfh[ks][mi], bh2);
                mma16816(dr[mi], qfh[ks][mi], bl2);
                mma16816(dr[mi], al4, bh2);
            }
        }
        #pragma unroll
        for (int mi = 0; mi < 2; mi++) {
            int q = mi * 16 + g;
            int r = nt * 8 + 2 * t;
            if (r < RR)     sW[q * WP + r]           = dr[mi][0];
            if (r + 1 < RR) sW[q * WP + r + 1]       = dr[mi][1];
            if (r < RR)     sW[(q + 8) * WP + r]     = dr[mi][2];
            if (r + 1 < RR) sW[(q + 8) * WP + r + 1] = dr[mi][3];
        }
    }
    __syncthreads();

    // ---- scores: 8 chunks, exp fused in epilogue ----
    const float scale = 0.125f;
    float psum[2][2] = {};
    float ps0[2][2] = {};
    for (int kt = 0; kt < 8; kt++) {
        #pragma unroll
        for (int it = 0; it < 4; it++) {
            int i = tid + it * 512;
            int s = i >> 10, idx = i & 1023;
            int row = idx >> 3, c = (idx & 7) * 8;
            __nv_bfloat16* dst = s ? aL : aH;
            *(uint4*)&dst[row * KP + c] = kreg[it];
        }
        __syncthreads();
        if (kt < 7) {
            #pragma unroll
            for (int it = 0; it < 4; it++) {
                int i = tid + it * 512;
                int s = i >> 10, idx = i & 1023;
                int row = idx >> 3, c = (idx & 7) * 8;
                const __nv_bfloat16* src = s ? KsL : KsH;
                kreg[it] = *(const uint4*)&src[((size_t)(b * SS) + (kt + 1) * 128 + row) * DD + h * DH + c];
            }
        }

        float dacc[2][4] = {};
        #pragma unroll
        for (int ks = 0; ks < 4; ks++) {
            int kk = ks * 16 + 2 * t;
            int rb = (warp * 8 + g) * KP;
            uint32_t bh2[2] = {*(uint32_t*)&aH[rb + kk], *(uint32_t*)&aH[rb + kk + 8]};
            uint32_t bl2[2] = {*(uint32_t*)&aL[rb + kk], *(uint32_t*)&aL[rb + kk + 8]};
            #pragma unroll
            for (int mi = 0; mi < 2; mi++) {
                int r0 = (mi * 16 + g) * KP, r1 = r0 + 8 * KP;
                uint32_t al4[4] = {*(uint32_t*)&qL[r0 + kk], *(uint32_t*)&qL[r1 + kk],
                                   *(uint32_t*)&qL[r0 + kk + 8], *(uint32_t*)&qL[r1 + kk + 8]};
                mma16816(dacc[mi], qfh[ks][mi], bh2);
                mma16816(dacc[mi], qfh[ks][mi], bl2);
                mma16816(dacc[mi], al4, bh2);
            }
        }
        #pragma unroll
        for (int mi = 0; mi < 2; mi++) {
            int q = mi * 16 + g;
            int gk = kt * 128 + warp * 8 + 2 * t;
            #pragma unroll
            for (int rr = 0; rr < 2; rr++) {
                int qq = q + rr * 8;
                int qg = q0 + qq;
                int rel0 = min(max(gk - qg,     -KWIN), KWIN) + KWIN;
                int rel1 = min(max(gk + 1 - qg, -KWIN), KWIN) + KWIN;
                float e0 = __expf((dacc[mi][rr * 2]     + sW[qq * WP + rel0]) * scale);
                float e1 = __expf((dacc[mi][rr * 2 + 1] + sW[qq * WP + rel1]) * scale);
                sS[qq * SSTR + gk]     = e0;
                sS[qq * SSTR + gk + 1] = e1;
                psum[mi][rr] += e0 + e1;
                if (gk     <= qg - KWIN) ps0[mi][rr] += e0;
                if (gk + 1 <= qg - KWIN) ps0[mi][rr] += e1;
            }
        }
        __syncthreads();
    }

    // prefetch V chunk 0
    uint4 vreg[4];
    #pragma unroll
    for (int it = 0; it < 4; it++) {
        int i = tid + it * 512;
        int s = i >> 10, idx = i & 1023;
        int d = idx >> 4, g4 = (idx & 15) * 4;
        const uint32_t* src = s ? vtL : vtH;
        vreg[it] = *(const uint4*)&src[((size_t)bh * DH + d) * (SS / 2) + g4];
    }

    // ---- reduce row sums (4-lane shuffle + smem atomics) ----
    {
        #pragma unroll
        for (int mi = 0; mi < 2; mi++)
            #pragma unroll
            for (int rr = 0; rr < 2; rr++) {
                psum[mi][rr] += __shfl_xor_sync(0xffffffffu, psum[mi][rr], 1, 4);
                psum[mi][rr] += __shfl_xor_sync(0xffffffffu, psum[mi][rr], 2, 4);
                ps0[mi][rr]  += __shfl_xor_sync(0xffffffffu, ps0[mi][rr],  1, 4);
                ps0[mi][rr]  += __shfl_xor_sync(0xffffffffu, ps0[mi][rr],  2, 4);
            }
        if (t == 0) {
            #pragma unroll
            for (int mi = 0; mi < 2; mi++)
                #pragma unroll
                for (int rr = 0; rr < 2; rr++) {
                    int q = mi * 16 + g + rr * 8;
                    atomicAdd(&sSum[q], psum[mi][rr]);
                    atomicAdd(&sS0[q],  ps0[mi][rr]);
                }
        }
    }
    __syncthreads();
    if (tid < 32) {
        sInv[tid] = 1.f / sSum[tid];
        sW[tid * WP + 0] = sS0[tid];
    }
    __syncthreads();

    // ---- write attn (normalized, float4) ----
    const int qrow = tid >> 4;
    const int s16  = tid & 15;
    {
        float* aout = attn_out + ((size_t)bh * SS + q0) * SS;
        for (int i = tid; i < 8192; i += 512) {
            int qq = i >> 8, k4 = (i & 255) * 4;
            float4 v = *(float4*)&sS[qq * SSTR + k4];
            float s = sInv[qq];
            v.x *= s; v.y *= s; v.z *= s; v.w *= s;
            *(float4*)&aout[(size_t)qq * SS + k4] = v;
        }
    }

    // ---- w buckets (middle fill + s1 derived; no prefix scan) ----
    {
        const int qg = q0 + qrow;
        float mid = 0.f;
        for (int r = 1 + s16; r <= 127; r += 16) {
            int k = qg - KWIN + r;
            float v = (k >= 0 && k < SS) ? sS[qrow * SSTR + k] : 0.f;
            sW[qrow * WP + r] = v;
            mid += v;
        }
        #pragma unroll
        for (int off = 1; off < 16; off <<= 1)
            mid += __shfl_xor_sync(0xffffffffu, mid, off, 16);
        if (s16 == 0)
            sW[qrow * WP + 128] = sSum[qrow] - sW[qrow * WP + 0] - mid;
        for (int i = tid; i < 32 * 31; i += 512) {
            int q = i / 31, r = 129 + (i % 31);
            sW[q * WP + r] = 0.f;
        }
    }
    __syncthreads();

    // ---- PV: 8 chunks; warp = (wn 0..3: 16 d-cols, hf 0..3: k-quarter) ----
    const int wn = warp >> 2, hf = warp & 3;
    float oacc[2][2][4] = {};
    for (int vt = 0; vt < 8; vt++) {
        #pragma unroll
        for (int it = 0; it < 4; it++) {
            int i = tid + it * 512;
            int s = i >> 10, idx = i & 1023;
            int d = idx >> 4, g4 = (idx & 15) * 4;
            uint32_t* dst = s ? vL : vH;
            *(uint4*)&dst[d * VP + g4] = vreg[it];
        }
        for (int i = tid; i < 2048; i += 512) {
            int q = i >> 6, c2 = (i & 63) * 2;
            float2 v = *(float2*)&sS[q * SSTR + vt * 128 + c2];
            uint32_t hpk, lpk;
            asm("cvt.rn.bf16x2.f32 %0, %1, %2;" : "=r"(hpk) : "f"(v.y), "f"(v.x));
            float h0 = __uint_as_float(hpk << 16);
            float h1 = __uint_as_float(hpk & 0xffff0000u);
            asm("cvt.rn.bf16x2.f32 %0, %1, %2;" : "=r"(lpk) : "f"(v.y - h1), "f"(v.x - h0));
            *(uint32_t*)&pH[q * PP + c2] = hpk;
            *(uint32_t*)&pL[q * PP + c2] = lpk;
        }
        __syncthreads();
        if (vt < 7) {
            #pragma unroll
            for (int it = 0; it < 4; it++) {
                int i = tid + it * 512;
                int s = i >> 10, idx = i & 1023;
                int d = idx >> 4, g4 = (idx & 15) * 4;
                const uint32_t* src = s ? vtL : vtH;
                vreg[it] = *(const uint4*)&src[((size_t)bh * DH + d) * (SS / 2) + (vt + 1) * 64 + g4];
            }
        }

        #pragma unroll
        for (int ks = 0; ks < 2; ks++) {
            int kb = hf * 32 + ks * 16 + 2 * t;
            int widx = hf * 16 + ks * 8 + t;
            uint32_t bh2[2][2], bl2[2][2];
            #pragma unroll
            for (int ni = 0; ni < 2; ni++) {
                int vrow = (wn * 16 + ni * 8 + g) * VP;
                bh2[ni][0] = vH[vrow + widx];  bh2[ni][1] = vH[vrow + widx + 4];
                bl2[ni][0] = vL[vrow + widx];  bl2[ni][1] = vL[vrow + widx + 4];
            }
            #pragma unroll
            for (int mi = 0; mi < 2; mi++) {
                int r0 = (mi * 16 + g) * PP, r1 = r0 + 8 * PP;
                uint32_t ah4[4] = {*(uint32_t*)&pH[r0 + kb], *(uint32_t*)&pH[r1 + kb],
                                   *(uint32_t*)&pH[r0 + kb + 8], *(uint32_t*)&pH[r1 + kb + 8]};
                uint32_t al4[4] = {*(uint32_t*)&pL[r0 + kb], *(uint32_t*)&pL[r1 + kb],
                                   *(uint32_t*)&pL[r0 + kb + 8], *(uint32_t*)&pL[r1 + kb + 8]};
                #pragma unroll
                for (int ni = 0; ni < 2; ni++) {
                    mma16816(oacc[mi][ni], ah4, bh2[ni]);
                    mma16816(oacc[mi][ni], ah4, bl2[ni]);
                    mma16816(oacc[mi][ni], al4, bh2[ni]);
                }
            }
        }
        __syncthreads();
    }

    // ---- extra chunk: w @ embV_h (hf 0,1 only; 2x80 cols) ----
    {
        for (int i = tid; i < 640; i += 512) {
            int p = i >> 3, dg = i & 7;
            int r0 = 2 * p, r1 = 2 * p + 1;
            float v0[8] = {}, v1[8] = {};
            if (r0 < RR) {
                float4 x = *(const float4*)&embV[(size_t)r0 * DD + h * DH + dg * 8];
                float4 y = *(const float4*)&embV[(size_t)r0 * DD + h * DH + dg * 8 + 4];
                v0[0]=x.x; v0[1]=x.y; v0[2]=x.z; v0[3]=x.w; v0[4]=y.x; v0[5]=y.y; v0[6]=y.z; v0[7]=y.w;
            }
            if (r1 < RR) {
                float4 x = *(const float4*)&embV[(size_t)r1 * DD + h * DH + dg * 8];
                float4 y = *(const float4*)&embV[(size_t)r1 * DD + h * DH + dg * 8 + 4];
                v1[0]=x.x; v1[1]=x.y; v1[2]=x.z; v1[3]=x.w; v1[4]=y.x; v1[5]=y.y; v1[6]=y.z; v1[7]=y.w;
            }
            #pragma unroll
            for (int j = 0; j < 8; j++) {
                __nv_bfloat16 h0 = __float2bfloat16(v0[j]);
                __nv_bfloat16 h1 = __float2bfloat16(v1[j]);
                __nv_bfloat16 l0 = __float2bfloat16(v0[j] - __bfloat162float(h0));
                __nv_bfloat16 l1 = __float2bfloat16(v1[j] - __bfloat162float(h1));
                vH[(dg * 8 + j) * VP + p] =
                    (uint32_t)__bfloat16_as_ushort(h0) | ((uint32_t)__bfloat16_as_ushort(h1) << 16);
                vL[(dg * 8 + j) * VP + p] =
                    (uint32_t)__bfloat16_as_ushort(l0) | ((uint32_t)__bfloat16_as_ushort(l1) << 16);
            }
        }
        for (int i = tid; i < 2560; i += 512) {
            int q = i / 80, c2 = (i % 80) * 2;
            float2 v = *(float2*)&sW[q * WP + c2];
            uint32_t hpk, lpk;
            asm("cvt.rn.bf16x2.f32 %0, %1, %2;" : "=r"(hpk) : "f"(v.y), "f"(v.x));
            float h0 = __uint_as_float(hpk << 16);
            float h1 = __uint_as_float(hpk & 0xffff0000u);
            asm("cvt.rn.bf16x2.f32 %0, %1, %2;" : "=r"(lpk) : "f"(v.y - h1), "f"(v.x - h0));
            *(uint32_t*)&pH[q * PP + c2] = hpk;
            *(uint32_t*)&pL[q * PP + c2] = lpk;
        }
        __syncthreads();

        if (hf < 2) {
            #pragma unroll
            for (int ks = 0; ks < 5; ks++) {
                int kb = hf * 80 + ks * 16 + 2 * t;
                int widx = hf * 40 + ks * 8 + t;
                uint32_t bh2[2][2], bl2[2][2];
                #pragma unroll
                for (int ni = 0; ni < 2; ni++) {
                    int vrow = (wn * 16 + ni * 8 + g) * VP;
                    bh2[ni][0] = vH[vrow + widx];  bh2[ni][1] = vH[vrow + widx + 4];
                    bl2[ni][0] = vL[vrow + widx];  bl2[ni][1] = vL[vrow + widx + 4];
                }
                #pragma unroll
                for (int mi = 0; mi < 2; mi++) {
                    int r0 = (mi * 16 + g) * PP, r1 = r0 + 8 * PP;
                    uint32_t ah4[4] = {*(uint32_t*)&pH[r0 + kb], *(uint32_t*)&pH[r1 + kb],
                                       *(uint32_t*)&pH[r0 + kb + 8], *(uint32_t*)&pH[r1 + kb + 8]};
                    uint32_t al4[4] = {*(uint32_t*)&pL[r0 + kb], *(uint32_t*)&pL[r1 + kb],
                                       *(uint32_t*)&pL[r0 + kb + 8], *(uint32_t*)&pL[r1 + kb + 8]};
                    #pragma unroll
                    for (int ni = 0; ni < 2; ni++) {
                        mma16816(oacc[mi][ni], ah4, bh2[ni]);
                        mma16816(oacc[mi][ni], ah4, bl2[ni]);
                        mma16816(oacc[mi][ni], al4, bh2[ni]);
                    }
                }
            }
        }
        __syncthreads();
    }

    // ---- reduce 4 hf partials (two 2-way rounds, staging in pH/pL region) ----
    {
        if (hf & 1) {
            int slot = hf >> 1;
            #pragma unroll
            for (int mi = 0; mi < 2; mi++)
                #pragma unroll
                for (int ni = 0; ni < 2; ni++) {
                    int q = mi * 16 + g, dc = wn * 16 + ni * 8 + 2 * t;
                    stg[slot * 2048 + q * 64 + dc]           = oacc[mi][ni][0];
                    stg[slot * 2048 + q * 64 + dc + 1]       = oacc[mi][ni][1];
                    stg[slot * 2048 + (q + 8) * 64 + dc]     = oacc[mi][ni][2];
                    stg[slot * 2048 + (q + 8) * 64 + dc + 1] = oacc[mi][ni][3];
                }
        }
        __syncthreads();
        if (!(hf & 1)) {
            int slot = hf >> 1;
            #pragma unroll
            for (int mi = 0; mi < 2; mi++)
                #pragma unroll
                for (int ni = 0; ni < 2; ni++) {
                    int q = mi * 16 + g, dc = wn * 16 + ni * 8 + 2 * t;
                    oacc[mi][ni][0] += stg[slot * 2048 + q * 64 + dc];
                    oacc[mi][ni][1] += stg[slot * 2048 + q * 64 + dc + 1];
                    oacc[mi][ni][2] += stg[slot * 2048 + (q + 8) * 64 + dc];
                    oacc[mi][ni][3] += stg[slot * 2048 + (q + 8) * 64 + dc + 1];
                }
        }
        __syncthreads();
        if (hf == 2) {
            #pragma unroll
            for (int mi = 0; mi < 2; mi++)
                #pragma unroll
                for (int ni = 0; ni < 2; ni++) {
                    int q = mi * 16 + g, dc = wn * 16 + ni * 8 + 2 * t;
                    stg[q * 64 + dc]           = oacc[mi][ni][0];
                    stg[q * 64 + dc + 1]       = oacc[mi][ni][1];
                    stg[(q + 8) * 64 + dc]     = oacc[mi][ni][2];
                    stg[(q + 8) * 64 + dc + 1] = oacc[mi][ni][3];
                }
        }
        __syncthreads();
        if (hf == 0) {
            #pragma unroll
            for (int mi = 0; mi < 2; mi++)
                #pragma unroll
                for (int ni = 0; ni < 2; ni++) {
                    int q = mi * 16 + g, dc = wn * 16 + ni * 8 + 2 * t;
                    float v00 = (oacc[mi][ni][0] + stg[q * 64 + dc])           * sInv[q];
                    float v01 = (oacc[mi][ni][1] + stg[q * 64 + dc + 1])       * sInv[q];
                    float v10 = (oacc[mi][ni][2] + stg[(q + 8) * 64 + dc])     * sInv[q + 8];
                    float v11 = (oacc[mi][ni][3] + stg[(q + 8) * 64 + dc + 1]) * sInv[q + 8];
                    uint32_t hp0, lp0, hp1, lp1;
                    asm("cvt.rn.bf16x2.f32 %0, %1, %2;" : "=r"(hp0) : "f"(v01), "f"(v00));
                    asm("cvt.rn.bf16x2.f32 %0, %1, %2;" : "=r"(hp1) : "f"(v11), "f"(v10));
                    float h00 = __uint_as_float(hp0 << 16);
                    float h01 = __uint_as_float(hp0 & 0xffff0000u);
                    float h10 = __uint_as_float(hp1 << 16);
                    float h11 = __uint_as_float(hp1 & 0xffff0000u);
                    asm("cvt.rn.bf16x2.f32 %0, %1, %2;" : "=r"(lp0) : "f"(v01 - h01), "f"(v00 - h00));
                    asm("cvt.rn.bf16x2.f32 %0, %1, %2;" : "=r"(lp1) : "f"(v11 - h11), "f"(v10 - h10));
                    size_t d0 = ((size_t)(b * SS) + q0 + q) * DD + h * DH + dc;
                    size_t d1 = ((size_t)(b * SS) + q0 + q + 8) * DD + h * DH + dc;
                    *(uint32_t*)&ctxH[d0] = hp0;
                    *(uint32_t*)&ctxL[d0] = lp0;
                    *(uint32_t*)&ctxH[d1] = hp1;
                    *(uint32_t*)&ctxL[d1] = lp1;
                }
        }
    }
}

// ---------------- launch ----------------
extern "C" void kernel_launch(void* const* d_in, const int* in_sizes, int n_in,
                              void* d_out, int out_size)
{
    const float* query = (const float*)d_in[0];
    const float* key   = (const float*)d_in[1];
    const float* value = (const float*)d_in[2];
    const float* WQ_w  = (const float*)d_in[3];
    const float* WQ_b  = (const float*)d_in[4];
    const float* WK_w  = (const float*)d_in[5];
    const float* WK_b  = (const float*)d_in[6];
    const float* WV_w  = (const float*)d_in[7];
    const float* WV_b  = (const float*)d_in[8];
    const float* WO_w  = (const float*)d_in[9];
    const float* WO_b  = (const float*)d_in[10];
    const float* embK  = (const float*)d_in[11];
    const float* embV  = (const float*)d_in[12];

    float* out = (float*)d_out;                       // [B,S,D]
    float* attn = out + (size_t)BB * SS * DD;         // [B,H,S,S]

    static float *Qp = nullptr, *Kp, *Vp;
    static __nv_bfloat16 *qh, *ql, *kh, *kl, *vh, *vl, *ch, *cl;
    static __nv_bfloat16 *wqh, *wql, *wkh, *wkl, *wvh, *wvl, *woh, *wol;
    static uint32_t *vtH, *vtL;
    if (!Qp) {
        cudaGetSymbolAddress((void**)&Qp, g_Qp);
        cudaGetSymbolAddress((void**)&Kp, g_Kp);
        cudaGetSymbolAddress((void**)&Vp, g_Vp);
        cudaGetSymbolAddress((void**)&qh, g_qh);   cudaGetSymbolAddress((void**)&ql, g_ql);
        cudaGetSymbolAddress((void**)&kh, g_kh);   cudaGetSymbolAddress((void**)&kl, g_kl);
        cudaGetSymbolAddress((void**)&vh, g_vh);   cudaGetSymbolAddress((void**)&vl, g_vl);
        cudaGetSymbolAddress((void**)&ch, g_ch);   cudaGetSymbolAddress((void**)&cl, g_cl);
        cudaGetSymbolAddress((void**)&wqh, g_wqh); cudaGetSymbolAddress((void**)&wql, g_wql);
        cudaGetSymbolAddress((void**)&wkh, g_wkh); cudaGetSymbolAddress((void**)&wkl, g_wkl);
        cudaGetSymbolAddress((void**)&wvh, g_wvh); cudaGetSymbolAddress((void**)&wvl, g_wvl);
        cudaGetSymbolAddress((void**)&woh, g_woh); cudaGetSymbolAddress((void**)&wol, g_wol);
        cudaGetSymbolAddress((void**)&vtH, g_vtH); cudaGetSymbolAddress((void**)&vtL, g_vtL);
        cudaFuncSetAttribute(attn_mma,
                             cudaFuncAttributeMaxDynamicSharedMemorySize, ASM_BYTES);
        cudaFuncSetAttribute(gemm_qkv,
                             cudaFuncAttributeMaxDynamicSharedMemorySize, GSMB);
        cudaFuncSetAttribute(gemm_o,
                             cudaFuncAttributeMaxDynamicSharedMemorySize, GSMB);
    }

    __nv_bfloat16* QsH = (__nv_bfloat16*)Qp;  __nv_bfloat16* QsL = QsH + (size_t)MTOT * DD;
    __nv_bfloat16* KsH = (__nv_bfloat16*)Kp;  __nv_bfloat16* KsL = KsH + (size_t)MTOT * DD;
    __nv_bfloat16* VsH = (__nv_bfloat16*)Vp;  __nv_bfloat16* VsL = VsH + (size_t)MTOT * DD;

    const int NIN = MTOT * DD;
    const int NW  = DD * DD;

    split_all_kernel<<<dim3(NIN / 4 / 256, 7), 256>>>(
        query, qh, ql, key, kh, kl, value, vh, vl,
        WQ_w, wqh, wql, WK_w, wkh, wkl, WV_w, wvh, wvl, WO_w, woh, wol,
        NIN, NW);
    gemm_qkv<<<dim3(DD / 128, MTOT / 64, 3), 256, GSMB>>>(
        qh, ql, wqh, wql, WQ_b, QsH, QsL,
        kh, kl, wkh, wkl, WK_b, KsH, KsL,
        vh, vl, wvh, wvl, WV_b, VsH, VsL);
    vtrans_kernel<<<BB * HH * 8, 256>>>(VsH, VsL, vtH, vtL);
    attn_mma<<<BB * HH * (SS / 32), 512, ASM_BYTES>>>(
        QsH, QsL, KsH, KsL, vtH, vtL, embK, embV, attn, ch, cl);
    gemm_o<<<dim3(DD / 128, MTOT / 64), 256, GSMB>>>(ch, cl, woh, wol, WO_b, out);
}